// round 17
// baseline (speedup 1.0000x reference)
#include <cuda_runtime.h>
#include <cuda_bf16.h>
#include <cstdint>

#define N_TOK   16384      // B*T
#define EDIM    1024
#define DHEAD   32
#define MFEAT   256

// ---------------- scratch (__device__ globals; no allocation) ----------------
// W int8 2-digit, block-scaled per (n, 64-K chunk). Per chunk: 64 rows x 128B:
// 16B chunks 0-3 = digit0 (k 0..63), 4-7 = digit1; chunk index XOR (n&7).
__device__ uint8_t W8_g[16 * 64 * 128];
__device__ float   sw_g[16 * 64];          // [chunk][n] scale = max|W|/127

__device__ __forceinline__ uint32_t smem_u32(const void* p) {
    uint32_t a;
    asm("{ .reg .u64 t; cvta.to.shared.u64 t, %1; cvt.u32.u64 %0, t; }" : "=r"(a) : "l"(p));
    return a;
}
__device__ __forceinline__ void ldsm_x4(uint32_t* r, uint32_t a) {
    asm volatile("ldmatrix.sync.aligned.m8n8.x4.shared.b16 {%0,%1,%2,%3}, [%4];"
                 : "=r"(r[0]), "=r"(r[1]), "=r"(r[2]), "=r"(r[3]) : "r"(a));
}
__device__ __forceinline__ void mma_bf16(float* c, const uint32_t* a, uint32_t b0, uint32_t b1) {
    asm volatile("mma.sync.aligned.m16n8k16.row.col.f32.bf16.bf16.f32 "
                 "{%0,%1,%2,%3}, {%4,%5,%6,%7}, {%8,%9}, {%0,%1,%2,%3};"
                 : "+f"(c[0]), "+f"(c[1]), "+f"(c[2]), "+f"(c[3])
                 : "r"(a[0]), "r"(a[1]), "r"(a[2]), "r"(a[3]), "r"(b0), "r"(b1));
}
__device__ __forceinline__ void mma_s8(int* c, const uint32_t* a, uint32_t b0, uint32_t b1) {
    asm volatile("mma.sync.aligned.m16n8k32.row.col.s32.s8.s8.s32 "
                 "{%0,%1,%2,%3}, {%4,%5,%6,%7}, {%8,%9}, {%0,%1,%2,%3};"
                 : "+r"(c[0]), "+r"(c[1]), "+r"(c[2]), "+r"(c[3])
                 : "r"(a[0]), "r"(a[1]), "r"(a[2]), "r"(a[3]), "r"(b0), "r"(b1));
}
__device__ __forceinline__ void cvtpair(float x, float y, uint32_t& h, uint32_t& l) {
    __nv_bfloat162 hh = __float22bfloat162_rn(make_float2(x, y));
    float2 f = __bfloat1622float2(hh);
    __nv_bfloat162 ll = __float22bfloat162_rn(make_float2(x - f.x, y - f.y));
    h = *(uint32_t*)&hh;
    l = *(uint32_t*)&ll;
}
__device__ __forceinline__ void cp_async16(uint32_t dst, const void* src) {
    asm volatile("cp.async.cg.shared.global [%0], [%1], 16;" :: "r"(dst), "l"(src) : "memory");
}
#define CP_COMMIT()  asm volatile("cp.async.commit_group;" ::: "memory")
#define CP_WAIT(n)   asm volatile("cp.async.wait_group %0;" :: "n"(n) : "memory")

// ---------------- kernel 0: W -> block-scaled int8 digits, pre-swizzled ------
__global__ __launch_bounds__(256) void wprep_kernel(
    const float* __restrict__ Wq, const float* __restrict__ Wk)
{
    int idx = blockIdx.x * 256 + threadIdx.x;   // 0..1023
    int c = idx >> 6, n = idx & 63;
    float v[64];
    float m = 0.f;
    #pragma unroll
    for (int kk = 0; kk < 64; kk++) {
        int k = c * 64 + kk;
        float f = (n < 32) ? Wq[(size_t)k * 32 + n] : Wk[(size_t)k * 32 + (n - 32)];
        v[kk] = f;
        m = fmaxf(m, fabsf(f));
    }
    m = fmaxf(m, 1e-20f);
    sw_g[c * 64 + n] = m * (1.f / 127.f);
    float inv = 127.f / m;
    uint8_t* base = W8_g + (size_t)c * 8192 + n * 128;
    #pragma unroll
    for (int ch = 0; ch < 4; ch++) {            // 16 k-values per 16B chunk
        uint32_t d0[4], d1[4];
        #pragma unroll
        for (int wv = 0; wv < 4; wv++) {
            uint32_t p0 = 0, p1 = 0;
            #pragma unroll
            for (int e = 0; e < 4; e++) {
                float t = v[ch * 16 + wv * 4 + e] * inv;
                int a = __float2int_rn(t);
                int b = __float2int_rn((t - (float)a) * 256.f);
                b = min(127, max(-128, b));
                p0 |= (uint32_t)(a & 255) << (8 * e);
                p1 |= (uint32_t)(b & 255) << (8 * e);
            }
            d0[wv] = p0; d1[wv] = p1;
        }
        *(uint4*)(base + ((uint32_t)(ch ^ (n & 7)) << 4))       = make_uint4(d0[0], d0[1], d0[2], d0[3]);
        *(uint4*)(base + ((uint32_t)((4 + ch) ^ (n & 7)) << 4)) = make_uint4(d1[0], d1[1], d1[2], d1[3]);
    }
}

// ---------------- fused kernel: int8 projection + bf16 features --------------
// 256 thr / 8 warps, M=128 tokens/CTA, grid 128 (R13 skeleton).
// Per 64-K chunk: x quantized in-staging to 2-digit int8 (per-row scale via
// shfl); 48 IMMA m16n8k32 replace 96 HMMA; int32 partials dequantized into
// fp32 masters per chunk. Feat phase = validated bf16 path.
#define SM_A      0              // 16KB int8 A (phase2: zq 128x32 f32)
#define SM_B      16384          // 2 bufs x 8KB (phase2: zk)
#define SM_SX     32768          // float[128] per-row x scale
#define SM_SW     33280          // float[16*64] W scales
#define SM_WSH    37376          // phase2: uint32[256*20]
#define SM_WSL    57856
#define SMEM_SZ   78336

__global__ __launch_bounds__(256, 1) void fused_kernel(
    const float* __restrict__ x,
    const float* __restrict__ bq, const float* __restrict__ bk,
    const float* __restrict__ w, float* __restrict__ out)
{
    extern __shared__ __align__(16) char sm[];
    float* zq   = (float*)(sm + SM_A);          // phase2 alias over A
    float* zk   = (float*)(sm + SM_B);          // phase2 alias over B
    float* sxSm = (float*)(sm + SM_SX);
    float* swSm = (float*)(sm + SM_SW);
    uint32_t* wsh = (uint32_t*)(sm + SM_WSH);
    uint32_t* wsl = (uint32_t*)(sm + SM_WSL);

    const int tid = threadIdx.x;
    const int wid = tid >> 5, lid = tid & 31;
    const int row0 = blockIdx.x * 128;

    const uint32_t smb = smem_u32(sm);
    const uint32_t sA = smb + SM_A;
    const uint32_t sB = smb + SM_B;

    const int mw = (wid >> 1) * 32;       // warp's 32-row block
    const int h  = wid & 1;               // dim-half
    const int g = lid >> 2, t = lid & 3;

    float acc[2][4][4];
    #pragma unroll
    for (int ms = 0; ms < 2; ms++)
        #pragma unroll
        for (int j = 0; j < 4; j++)
            acc[ms][j][0] = acc[ms][j][1] = acc[ms][j][2] = acc[ms][j][3] = 0.f;

    // x staging: 1024 8-float groups over 256 threads
    int cr[4], cc8[4];
    #pragma unroll
    for (int i = 0; i < 4; i++) {
        int idx = i * 256 + tid;
        cr[i]  = idx >> 3;
        cc8[i] = idx & 7;
    }
    const int i4 = lid >> 3;
    const int l7 = lid & 7;

    // ---- prologue: sw table, cp.async B0, LDG x0 ----
    #pragma unroll
    for (int i = 0; i < 4; i++) swSm[i * 256 + tid] = sw_g[i * 256 + tid];
    #pragma unroll
    for (int i = 0; i < 2; i++) {
        int u = i * 256 + tid;
        cp_async16(sB + u * 16, (const uint8_t*)W8_g + u * 16);
    }
    CP_COMMIT();

    float4 xa[4][2];
    #pragma unroll
    for (int i = 0; i < 4; i++) {
        const float4* p = (const float4*)&x[(size_t)(row0 + cr[i]) * EDIM + cc8[i] * 8];
        xa[i][0] = p[0]; xa[i][1] = p[1];
    }

    // ================= mainloop: 16 chunks of K=64 =================
    #pragma unroll 1
    for (int c = 0; c < 16; c++) {
        // ---- quantize + stage x chunk (per-row scale via shfl over 8 lanes) --
        #pragma unroll
        for (int i = 0; i < 4; i++) {
            float v[8] = {xa[i][0].x, xa[i][0].y, xa[i][0].z, xa[i][0].w,
                          xa[i][1].x, xa[i][1].y, xa[i][1].z, xa[i][1].w};
            float m = fabsf(v[0]);
            #pragma unroll
            for (int e = 1; e < 8; e++) m = fmaxf(m, fabsf(v[e]));
            m = fmaxf(m, __shfl_xor_sync(0xffffffffu, m, 1));
            m = fmaxf(m, __shfl_xor_sync(0xffffffffu, m, 2));
            m = fmaxf(m, __shfl_xor_sync(0xffffffffu, m, 4));
            m = fmaxf(m, 1e-20f);
            float inv = 127.f / m;
            uint32_t w1[2] = {0u, 0u}, w2[2] = {0u, 0u};
            #pragma unroll
            for (int e = 0; e < 8; e++) {
                float tq = v[e] * inv;
                int a = __float2int_rn(tq);
                int b = __float2int_rn((tq - (float)a) * 256.f);
                b = min(127, max(-128, b));
                w1[e >> 2] |= (uint32_t)(a & 255) << (8 * (e & 3));
                w2[e >> 2] |= (uint32_t)(b & 255) << (8 * (e & 3));
            }
            int row = cr[i], gg = cc8[i];
            char* rb = sm + SM_A + row * 128;
            uint32_t c0 = (((uint32_t)(gg >> 1) ^ (row & 7)) << 4) + ((gg & 1) << 3);
            uint32_t c1 = (((uint32_t)(4 + (gg >> 1)) ^ (row & 7)) << 4) + ((gg & 1) << 3);
            *(uint2*)(rb + c0) = make_uint2(w1[0], w1[1]);
            *(uint2*)(rb + c1) = make_uint2(w2[0], w2[1]);
            if (gg == 0) sxSm[row] = m * (1.f / 127.f);
        }
        // ---- prefetch x_{c+1}; cp.async B_{c+1} ----
        if (c < 15) {
            #pragma unroll
            for (int i = 0; i < 4; i++) {
                const float4* p = (const float4*)&x[(size_t)(row0 + cr[i]) * EDIM + (c + 1) * 64 + cc8[i] * 8];
                xa[i][0] = p[0]; xa[i][1] = p[1];
            }
            const uint32_t db = sB + ((c + 1) & 1) * 8192;
            const uint8_t* gsrc = (const uint8_t*)W8_g + (size_t)(c + 1) * 8192;
            #pragma unroll
            for (int i = 0; i < 2; i++) {
                int u = i * 256 + tid;
                cp_async16(db + u * 16, gsrc + u * 16);
            }
            CP_COMMIT();
            CP_WAIT(1);
        } else {
            CP_WAIT(0);
        }
        __syncthreads();

        // ---- preload A fragments (both digits, both k32 groups) ----
        const uint32_t sBb = sB + (c & 1) * 8192;
        uint32_t A1[2][2][4], A2[2][2][4];
        #pragma unroll
        for (int ms = 0; ms < 2; ms++) {
            int r = mw + 16 * ms + ((i4 & 1) << 3) + l7;
            uint32_t rb = sA + (uint32_t)(r * 128);
            #pragma unroll
            for (int kg = 0; kg < 2; kg++) {
                ldsm_x4(A1[ms][kg], rb + (((uint32_t)(2 * kg + (i4 >> 1)) ^ l7) << 4));
                ldsm_x4(A2[ms][kg], rb + (((uint32_t)(4 + 2 * kg + (i4 >> 1)) ^ l7) << 4));
            }
        }
        float sxv[2][2];
        #pragma unroll
        for (int ms = 0; ms < 2; ms++) {
            sxv[ms][0] = sxSm[mw + 16 * ms + g];
            sxv[ms][1] = sxSm[mw + 16 * ms + 8 + g];
        }
        // ---- per n-tile: B frags (one ldsm_x4 per digit covers both kg) ----
        #pragma unroll
        for (int jj = 0; jj < 4; jj++) {
            const int tile = (jj < 2) ? (2 * h + jj) : (2 + 2 * h + jj);
            int nr = 8 * tile + l7;
            uint32_t nb = sBb + (uint32_t)(nr * 128);
            uint32_t Bd0[4], Bd1[4];
            ldsm_x4(Bd0, nb + (((uint32_t)i4 ^ l7) << 4));
            ldsm_x4(Bd1, nb + (((uint32_t)(4 + i4) ^ l7) << 4));

            int P1[2][4] = {{0,0,0,0},{0,0,0,0}};
            int P2[2][4] = {{0,0,0,0},{0,0,0,0}};
            #pragma unroll
            for (int ms = 0; ms < 2; ms++) {
                mma_s8(P1[ms], A1[ms][0], Bd0[0], Bd0[1]);   // X1*W1
                mma_s8(P1[ms], A1[ms][1], Bd0[2], Bd0[3]);
                mma_s8(P2[ms], A1[ms][0], Bd1[0], Bd1[1]);   // X1*W2
                mma_s8(P2[ms], A1[ms][1], Bd1[2], Bd1[3]);
                mma_s8(P2[ms], A2[ms][0], Bd0[0], Bd0[1]);   // X2*W1
                mma_s8(P2[ms], A2[ms][1], Bd0[2], Bd0[3]);
            }
            // dequantize into fp32 masters
            int n0 = tile * 8 + 2 * t;
            float sw0 = swSm[c * 64 + n0], sw1 = swSm[c * 64 + n0 + 1];
            #pragma unroll
            for (int ms = 0; ms < 2; ms++) {
                float s00 = sxv[ms][0] * sw0, s01 = sxv[ms][0] * sw1;
                float s10 = sxv[ms][1] * sw0, s11 = sxv[ms][1] * sw1;
                float f0 = fmaf((float)P2[ms][0], 1.f / 256.f, (float)P1[ms][0]);
                float f1 = fmaf((float)P2[ms][1], 1.f / 256.f, (float)P1[ms][1]);
                float f2 = fmaf((float)P2[ms][2], 1.f / 256.f, (float)P1[ms][2]);
                float f3 = fmaf((float)P2[ms][3], 1.f / 256.f, (float)P1[ms][3]);
                acc[ms][jj][0] = fmaf(f0, s00, acc[ms][jj][0]);
                acc[ms][jj][1] = fmaf(f1, s01, acc[ms][jj][1]);
                acc[ms][jj][2] = fmaf(f2, s10, acc[ms][jj][2]);
                acc[ms][jj][3] = fmaf(f3, s11, acc[ms][jj][3]);
            }
        }
        __syncthreads();
    }

    // ============ exchange: q,k (+bias) -> zq/zk smem (alias A/B) ============
    #pragma unroll
    for (int ms = 0; ms < 2; ms++) {
        const int lr0 = mw + 16 * ms + g, lr1 = lr0 + 8;
        #pragma unroll
        for (int jj = 0; jj < 2; jj++) {          // q tiles
            int col = 16 * h + 8 * jj + 2 * t;
            float2 b2 = *(const float2*)&bq[col];
            *(float2*)&zq[lr0 * 32 + col] = make_float2(acc[ms][jj][0] + b2.x, acc[ms][jj][1] + b2.y);
            *(float2*)&zq[lr1 * 32 + col] = make_float2(acc[ms][jj][2] + b2.x, acc[ms][jj][3] + b2.y);
        }
        #pragma unroll
        for (int jj = 2; jj < 4; jj++) {          // k tiles
            int col = 16 * h + 8 * (jj - 2) + 2 * t;
            float2 b2 = *(const float2*)&bk[col];
            *(float2*)&zk[lr0 * 32 + col] = make_float2(acc[ms][jj][0] + b2.x, acc[ms][jj][1] + b2.y);
            *(float2*)&zk[lr1 * 32 + col] = make_float2(acc[ms][jj][2] + b2.x, acc[ms][jj][3] + b2.y);
        }
    }
    // convert w into smem (1 row per thread)
    {
        const int row = tid;
        #pragma unroll
        for (int j = 0; j < 8; j++) {
            float4 v = *(const float4*)&w[(size_t)row * DHEAD + 4 * j];
            uint32_t h0, l0, h1, l1;
            cvtpair(v.x, v.y, h0, l0);
            cvtpair(v.z, v.w, h1, l1);
            wsh[row * 20 + 2 * j]     = h0;
            wsh[row * 20 + 2 * j + 1] = h1;
            wsl[row * 20 + 2 * j]     = l0;
            wsl[row * 20 + 2 * j + 1] = l1;
        }
    }
    __syncthreads();

    // ============ rebuild feat A-frags + s from zq/zk ============
    const int lr0 = wid * 16 + g, lr1 = lr0 + 8;
    uint32_t ah[2][4], al[2][4];
    float s0 = 0.f, s1 = 0.f;
    #pragma unroll
    for (int kg = 0; kg < 2; kg++) {
        #pragma unroll
        for (int hh = 0; hh < 2; hh++) {
            int col = kg * 16 + hh * 8 + 2 * t;
            float2 q0 = *(const float2*)&zq[lr0 * 32 + col];
            float2 k0 = *(const float2*)&zk[lr0 * 32 + col];
            float2 q1 = *(const float2*)&zq[lr1 * 32 + col];
            float2 k1 = *(const float2*)&zk[lr1 * 32 + col];
            s0 += q0.x * q0.x + q0.y * q0.y + k0.x * k0.x + k0.y * k0.y;
            s1 += q1.x * q1.x + q1.y * q1.y + k1.x * k1.x + k1.y * k1.y;
            cvtpair(q0.x + k0.x, q0.y + k0.y, ah[kg][2 * hh],     al[kg][2 * hh]);
            cvtpair(q1.x + k1.x, q1.y + k1.y, ah[kg][2 * hh + 1], al[kg][2 * hh + 1]);
        }
    }
    s0 += __shfl_xor_sync(0xffffffffu, s0, 1);
    s0 += __shfl_xor_sync(0xffffffffu, s0, 2);
    s1 += __shfl_xor_sync(0xffffffffu, s1, 1);
    s1 += __shfl_xor_sync(0xffffffffu, s1, 2);
    s0 *= 0.5f;
    s1 *= 0.5f;

    // ============ phase 2: features (32 n-tiles per warp) ============
    const int r0 = row0 + lr0;
    #pragma unroll 4
    for (int j = 0; j < 32; j++) {
        const int nb = 8 * j;
        const uint32_t* bhp = &wsh[(nb + g) * 20 + t];
        const uint32_t* blp = &wsl[(nb + g) * 20 + t];
        uint32_t bh0 = bhp[0], bh1 = bhp[4], bh2 = bhp[8], bh3 = bhp[12];
        uint32_t bl0 = blp[0], bl1 = blp[4], bl2 = blp[8], bl3 = blp[12];

        float cc[4] = {0.f, 0.f, 0.f, 0.f};
        mma_bf16(cc, ah[0], bh0, bh1);   // hi*hi
        mma_bf16(cc, ah[1], bh2, bh3);
        mma_bf16(cc, ah[0], bl0, bl1);   // hi*lo
        mma_bf16(cc, ah[1], bl2, bl3);
        mma_bf16(cc, al[0], bh0, bh1);   // lo*hi
        mma_bf16(cc, al[1], bh2, bh3);

        float r00 = 0.5f * (__expf(cc[0] - s0) + __expf(-cc[0] - s0));
        float r01 = 0.5f * (__expf(cc[1] - s0) + __expf(-cc[1] - s0));
        float r10 = 0.5f * (__expf(cc[2] - s1) + __expf(-cc[2] - s1));
        float r11 = 0.5f * (__expf(cc[3] - s1) + __expf(-cc[3] - s1));
        *(float2*)&out[(size_t)r0 * MFEAT + nb + 2 * t]       = make_float2(r00, r01);
        *(float2*)&out[(size_t)(r0 + 8) * MFEAT + nb + 2 * t] = make_float2(r10, r11);
    }
}

extern "C" void kernel_launch(void* const* d_in, const int* in_sizes, int n_in,
                              void* d_out, int out_size)
{
    const float* x  = (const float*)d_in[0];
    const float* Wq = (const float*)d_in[1];
    const float* bq = (const float*)d_in[2];
    const float* Wk = (const float*)d_in[3];
    const float* bk = (const float*)d_in[4];
    // d_in[5], d_in[6] = Wv, bv: unused (reference discards v)
    const float* w  = (const float*)d_in[7];
    float* out = (float*)d_out;

    static bool attr_set = false;   // idempotent host-side attribute
    if (!attr_set) {
        cudaFuncSetAttribute(fused_kernel, cudaFuncAttributeMaxDynamicSharedMemorySize, SMEM_SZ);
        attr_set = true;
    }
    wprep_kernel<<<4, 256>>>(Wq, Wk);
    fused_kernel<<<N_TOK / 128, 256, SMEM_SZ>>>(x, bq, bk, w, out);
}